// round 12
// baseline (speedup 1.0000x reference)
#include <cuda_runtime.h>
#include <cuda_bf16.h>
#include <cstdint>

#define N_SAMP  8192
#define EMB     128
#define NBINS   10
#define LBINS   11
#define HP      16
#define THREADS 512
#define CG      4                    // col groups (grid.x)
#define CTILE   64                   // cols per CTA tile
#define TPC     (N_SAMP / CG / CTILE)   // 32 col tiles per CTA
#define PB      272                  // smem tile row pitch in bytes (136 bf16)
#define A_SM    (128 * PB)           // 34816 B  (128 x 128 bf16)
#define B_SM    (CTILE * PB)         // 17408 B  (64 x 128 bf16)

// ---------------- device scratch ----------------
__device__ __nv_bfloat16 g_Xb[N_SAMP * EMB];   // bf16 X, row-major (K-major)
__device__ float g_all[N_SAMP * HP];           // bins 0..2,8..10 raw; 3..7 cumulative C[b]
__device__ float g_pos[N_SAMP * HP];           // positive-pair raw soft hist
__device__ int   g_cls[8192];

// ---------------- PTX helpers ----------------
static __device__ __forceinline__ uint32_t s2u(const void* p) {
    uint32_t a;
    asm("{ .reg .u64 t; cvta.to.shared.u64 t, %1; cvt.u32.u64 %0, t; }" : "=r"(a) : "l"(p));
    return a;
}
#define CP_ASYNC16(dst, src) \
    asm volatile("cp.async.cg.shared.global [%0], [%1], 16;" :: "r"(dst), "l"(src) : "memory")
#define CP_COMMIT() asm volatile("cp.async.commit_group;" ::: "memory")
#define CP_WAIT0()  asm volatile("cp.async.wait_group 0;" ::: "memory")

#define LDSM4(R, addr) \
    asm volatile("ldmatrix.sync.aligned.m8n8.x4.shared.b16 {%0,%1,%2,%3}, [%4];" \
        : "=r"((R)[0]), "=r"((R)[1]), "=r"((R)[2]), "=r"((R)[3]) : "r"(addr))

#define MMA16816(C, A, b0v, b1v) \
    asm volatile("mma.sync.aligned.m16n8k16.row.col.f32.bf16.bf16.f32 " \
        "{%0,%1,%2,%3},{%4,%5,%6,%7},{%8,%9},{%0,%1,%2,%3};" \
        : "+f"((C)[0]), "+f"((C)[1]), "+f"((C)[2]), "+f"((C)[3]) \
        : "r"((A)[0]), "r"((A)[1]), "r"((A)[2]), "r"((A)[3]), "r"(b0v), "r"(b1v))

// sat-FMA: clamp(a*5 + c, 0, 1)  == cumulative-histogram ramp
static __device__ __forceinline__ float fma_sat5(float a, float c) {
    float r;
    asm("fma.rn.sat.f32 %0, %1, %2, %3;" : "=f"(r) : "f"(a), "f"(5.0f), "f"(c));
    return r;
}

// ---------------- small kernels ----------------
__global__ void zero_kernel() {
    int i = blockIdx.x * blockDim.x + threadIdx.x;
    int stride = gridDim.x * blockDim.x;
    for (int idx = i; idx < N_SAMP * HP; idx += stride) { g_all[idx] = 0.0f; g_pos[idx] = 0.0f; }
    for (int idx = i; idx < 8192; idx += stride) g_cls[idx] = 0;
}

__global__ void prep_count_kernel(const float* __restrict__ X, const int* __restrict__ labels) {
    int i = blockIdx.x * blockDim.x + threadIdx.x;     // N_SAMP * 64
    if (i < N_SAMP * (EMB / 2)) {
        float2 v = ((const float2*)X)[i];
        ((__nv_bfloat162*)g_Xb)[i] = __float22bfloat162_rn(v);
    }
    if (i < N_SAMP) {
        int l = labels[i];
        if (l >= 0 && l < 8192) atomicAdd(&g_cls[l], 1);
    }
}

// rare-path handler (positive pairs ~1%, out-of-window tails ~1e-5)
static __device__ __noinline__ void rare_elem(float dot, int lab, int gcol, int grow, int mylab) {
    if (gcol == grow) return;                       // exclude diagonal
    float tv = fmaf(dot, -5.0f, 5.0f);              // 2.5 * dist2
    if (lab == mylab) {
        float tp = fmaxf(tv, 0.0f);
        int l0 = min((int)tp, 9);
        float fr = tp - (float)l0;
        atomicAdd(&g_pos[grow * HP + l0],     1.0f - fr);
        atomicAdd(&g_pos[grow * HP + l0 + 1], fr);
    }
    if (tv < 3.0f || tv > 7.0f) {                   // raw tail bins
        #pragma unroll
        for (int b = 0; b <= 2; b++) {
            float w = 1.0f - fabsf(tv - (float)b);
            if (w > 0.0f) atomicAdd(&g_all[grow * HP + b], w);
        }
        #pragma unroll
        for (int b = 8; b <= 10; b++) {
            float w = 1.0f - fabsf(tv - (float)b);
            if (w > 0.0f) atomicAdd(&g_all[grow * HP + b], w);
        }
    }
}

// ---------------- fused HMMA GEMM + sat-FMA cumulative soft-hist ----------------
// grid (CG, 64): blockIdx.y = 128-row block, blockIdx.x = group of TPC 64-col tiles.
// 16 warps, 8(m) x 2(n) warp grid, warp tile 16x32, CTA tile 128x64.
extern __shared__ char smem_raw[];

__global__ __launch_bounds__(THREADS, 2)
void hist_kernel(const int* __restrict__ labels) {
    const int tid  = threadIdx.x;
    const int lane = tid & 31;
    const int warp = tid >> 5;
    const int wm   = warp >> 1;          // 0..7: 16-row slice
    const int wn   = warp & 1;           // 0..1: 32-col half
    const int rb   = blockIdx.y;
    const int cg   = blockIdx.x;
    const int rowG = rb * 128;

    const uint32_t uS = s2u(smem_raw);
    const uint32_t uA = uS;
    const uint32_t uBb[2] = { uS + A_SM, uS + A_SM + B_SM };
    const uint32_t uLab = uS + A_SM + 2 * B_SM;          // int[2][CTILE]
    int* sLab = (int*)(smem_raw + A_SM + 2 * B_SM);

    // ---- load A tile (128x128) + B tile 0 (64x128) via cp.async ----
    {
        const char* gA = (const char*)(g_Xb + (size_t)rb * 128 * EMB);
        for (int i = tid; i < 2048; i += THREADS) {
            int row = i >> 4, c = i & 15;
            CP_ASYNC16(uA + row * PB + c * 16, gA + row * 256 + c * 16);
        }
        int sc = cg * (TPC * CTILE);
        const char* gB = (const char*)(g_Xb + (size_t)sc * EMB);
        for (int i = tid; i < 1024; i += THREADS) {
            int row = i >> 4, c = i & 15;
            CP_ASYNC16(uBb[0] + row * PB + c * 16, gB + row * 256 + c * 16);
        }
        if (tid < CTILE) sLab[tid] = labels[sc + tid];
    }
    CP_COMMIT();
    CP_WAIT0();
    __syncthreads();

    const int g  = lane >> 2;
    const int tq = lane & 3;

    int lrow[2], myLab[2];
    lrow[0] = wm * 16 + g;  lrow[1] = lrow[0] + 8;
    myLab[0] = labels[rowG + lrow[0]];
    myLab[1] = labels[rowG + lrow[1]];

    float h[2][5];                       // cumulative C[3..7] per row
    #pragma unroll
    for (int r = 0; r < 2; r++)
        #pragma unroll
        for (int b = 0; b < 5; b++) h[r][b] = 0.0f;

    const uint32_t aBase = uA + (uint32_t)((wm * 16 + (lane & 15)) * PB + (lane >> 4) * 16);
    const uint32_t bRowOff = (uint32_t)((wn * 32 + (lane & 7) + ((lane >> 4) & 1) * 8) * PB
                                        + ((lane >> 3) & 1) * 16);
    const uint32_t labCol = uLab + (uint32_t)((wn * 32 + tq * 2) * 4);

    #pragma unroll 1
    for (int t = 0; t < TPC; t++) {
        const int buf = t & 1;

        // prefetch B[t+1]
        if (t + 1 < TPC) {
            int sc = cg * (TPC * CTILE) + (t + 1) * CTILE;
            const char* gB = (const char*)(g_Xb + (size_t)sc * EMB);
            uint32_t dB = uBb[buf ^ 1];
            for (int i = tid; i < 1024; i += THREADS) {
                int row = i >> 4, c = i & 15;
                CP_ASYNC16(dB + row * PB + c * 16, gB + row * 256 + c * 16);
            }
            CP_COMMIT();
            if (tid < CTILE) sLab[(buf ^ 1) * CTILE + tid] = labels[sc + tid];
        }

        // ---- GEMM: 128x64 tile, warp computes 16x32 ----
        float acc[4][4];
        #pragma unroll
        for (int j = 0; j < 4; j++)
            #pragma unroll
            for (int e = 0; e < 4; e++) acc[j][e] = 0.0f;

        const uint32_t uBt = uBb[buf] + bRowOff;
        #pragma unroll
        for (int kc = 0; kc < 8; kc++) {
            uint32_t A0[4], B0[4], B1[4];
            LDSM4(A0, aBase + kc * 32);
            LDSM4(B0, uBt + kc * 32);             // n-tiles 0,1
            LDSM4(B1, uBt + 16 * PB + kc * 32);   // n-tiles 2,3
            MMA16816(acc[0], A0, B0[0], B0[1]);
            MMA16816(acc[1], A0, B0[2], B0[3]);
            MMA16816(acc[2], A0, B1[0], B1[1]);
            MMA16816(acc[3], A0, B1[2], B1[3]);
        }

        // ---- epilogue: cumulative sat-FMA binning of 16 dot products ----
        // C[b] += clamp((b+1) - t, 0, 1) = sat(5*dot + (b-4)),  b = 3..7
        const int colBase = cg * (TPC * CTILE) + t * CTILE;
        const uint32_t labT = labCol + (uint32_t)(buf * CTILE * 4);

        #pragma unroll
        for (int j = 0; j < 4; j++) {
            int cl0, cl1;
            asm("ld.shared.v2.u32 {%0,%1}, [%2];" : "=r"(cl0), "=r"(cl1)
                : "r"(labT + (uint32_t)(j * 32)));
            #pragma unroll
            for (int e = 0; e < 4; e++) {
                const int ri = e >> 1;
                const int li = e & 1;
                float dot = acc[j][e];
                #pragma unroll
                for (int b = 0; b < 5; b++)
                    h[ri][b] += fma_sat5(dot, (float)(b - 1));   // b-1 = (b+3)-4
                int clab = li ? cl1 : cl0;
                bool rare = (fabsf(dot) > 0.4f) | (clab == myLab[ri]);
                if (__builtin_expect(rare, 0)) {
                    int gcol = colBase + wn * 32 + j * 8 + tq * 2 + li;
                    rare_elem(dot, clab, gcol, rowG + lrow[ri], myLab[ri]);
                }
            }
        }

        CP_WAIT0();
        __syncthreads();
    }

    // flush cumulative hists (bins 3..7)
    #pragma unroll
    for (int ri = 0; ri < 2; ri++) {
        int grow = rowG + lrow[ri];
        #pragma unroll
        for (int b = 0; b < 5; b++)
            atomicAdd(&g_all[grow * HP + 3 + b], h[ri][b]);
    }
}

// ---------------- fused finalize + loss (single block) ----------------
__global__ void finalize_kernel(const int* __restrict__ labels, float* __restrict__ out) {
    __shared__ float sv[32], sn[32];
    float val = 0.0f, valid = 0.0f;
    for (int i = threadIdx.x; i < N_SAMP; i += 1024) {
        float4 a0 = *(const float4*)&g_all[i * HP + 0];
        float4 a1 = *(const float4*)&g_all[i * HP + 4];
        float4 a2 = *(const float4*)&g_all[i * HP + 8];
        // raw bins 0..2; cumulative C[3..7] (includes diagonal: exactly 1 each)
        float h0 = a0.x, h1 = a0.y, h2 = a0.z;
        float C3 = a0.w - 1.0f, C4 = a1.x - 1.0f, C5 = a1.y - 1.0f,
              C6 = a1.z - 1.0f, C7 = a1.w - 1.0f;
        float aA[12];
        aA[0] = h0; aA[1] = h1; aA[2] = h2;
        aA[3] = C3 - (h0 + h1 + h2);
        aA[4] = C4 - C3; aA[5] = C5 - C4; aA[6] = C6 - C5; aA[7] = C7 - C6;
        aA[8] = a2.x; aA[9] = a2.y; aA[10] = a2.z; aA[11] = 0.0f;
        float4 p0 = *(const float4*)&g_pos[i * HP + 0];
        float4 p1 = *(const float4*)&g_pos[i * HP + 4];
        float4 p2 = *(const float4*)&g_pos[i * HP + 8];
        float  pA[12] = {p0.x,p0.y,p0.z,p0.w,p1.x,p1.y,p1.z,p1.w,p2.x,p2.y,p2.z,0.0f};
        float Hp = 0.0f, H = 0.0f, ap = 0.0f;
        #pragma unroll
        for (int l = 0; l < LBINS; l++) {
            Hp += pA[l];
            H  += aA[l];
            if (H > 0.0f) ap += pA[l] * Hp / H;
        }
        int np = g_cls[labels[i]] - 1;
        if (np > 0) { val += ap / (float)np; valid += 1.0f; }
    }
    #pragma unroll
    for (int off = 16; off > 0; off >>= 1) {
        val   += __shfl_down_sync(0xffffffffu, val, off);
        valid += __shfl_down_sync(0xffffffffu, valid, off);
    }
    int warp = threadIdx.x >> 5, lane = threadIdx.x & 31;
    if (lane == 0) { sv[warp] = val; sn[warp] = valid; }
    __syncthreads();
    if (warp == 0) {
        val   = sv[lane];
        valid = sn[lane];
        #pragma unroll
        for (int off = 16; off > 0; off >>= 1) {
            val   += __shfl_down_sync(0xffffffffu, val, off);
            valid += __shfl_down_sync(0xffffffffu, valid, off);
        }
        if (lane == 0) out[0] = 1.0f - val / valid;
    }
}

// ---------------- launch ----------------
extern "C" void kernel_launch(void* const* d_in, const int* in_sizes, int n_in,
                              void* d_out, int out_size) {
    const float* X      = (const float*)d_in[0];
    const int*   labels = (const int*)d_in[1];
    float*       out    = (float*)d_out;

    const int SMEM = A_SM + 2 * B_SM + 2 * CTILE * (int)sizeof(int) + 64;  // ~70.3 KB
    cudaFuncSetAttribute(hist_kernel, cudaFuncAttributeMaxDynamicSharedMemorySize, SMEM);

    zero_kernel<<<256, 256>>>();
    prep_count_kernel<<<(N_SAMP * (EMB / 2) + 255) / 256, 256>>>(X, labels);

    dim3 grid(CG, 64);            // 256 CTAs, 2 per SM, single wave
    hist_kernel<<<grid, THREADS, SMEM>>>(labels);

    finalize_kernel<<<1, 1024>>>(labels, out);
}

// round 13
// speedup vs baseline: 1.0604x; 1.0604x over previous
#include <cuda_runtime.h>
#include <cuda_bf16.h>
#include <cstdint>

#define N_SAMP  8192
#define EMB     128
#define NBINS   10
#define LBINS   11
#define HP      16
#define THREADS 512
#define CG      8                    // col groups (grid.x)
#define CTILE   64                   // cols per CTA tile
#define TPC     (N_SAMP / CG / CTILE)   // 16 col tiles per CTA
#define PB      272                  // smem tile row pitch in bytes (136 bf16)
#define A_SM    (128 * PB)           // 34816 B  (128 x 128 bf16)
#define B_SM    (CTILE * PB)         // 17408 B  (64 x 128 bf16)

// ---------------- device scratch ----------------
__device__ __nv_bfloat16 g_Xb[N_SAMP * EMB];   // bf16 X, row-major (K-major)
__device__ float g_all[N_SAMP * HP];           // bins 0..2,8..10 raw; 3..7 cumulative C[b]
__device__ float g_pos[N_SAMP * HP];           // positive-pair raw soft hist
__device__ int   g_cls[8192];
__device__ float g_ap_sum;
__device__ float g_nvalid;

// ---------------- PTX helpers ----------------
static __device__ __forceinline__ uint32_t s2u(const void* p) {
    uint32_t a;
    asm("{ .reg .u64 t; cvta.to.shared.u64 t, %1; cvt.u32.u64 %0, t; }" : "=r"(a) : "l"(p));
    return a;
}
#define CP_ASYNC16(dst, src) \
    asm volatile("cp.async.cg.shared.global [%0], [%1], 16;" :: "r"(dst), "l"(src) : "memory")
#define CP_COMMIT() asm volatile("cp.async.commit_group;" ::: "memory")
#define CP_WAIT0()  asm volatile("cp.async.wait_group 0;" ::: "memory")

#define LDSM4(R, addr) \
    asm volatile("ldmatrix.sync.aligned.m8n8.x4.shared.b16 {%0,%1,%2,%3}, [%4];" \
        : "=r"((R)[0]), "=r"((R)[1]), "=r"((R)[2]), "=r"((R)[3]) : "r"(addr))

#define MMA16816(C, A, b0v, b1v) \
    asm volatile("mma.sync.aligned.m16n8k16.row.col.f32.bf16.bf16.f32 " \
        "{%0,%1,%2,%3},{%4,%5,%6,%7},{%8,%9},{%0,%1,%2,%3};" \
        : "+f"((C)[0]), "+f"((C)[1]), "+f"((C)[2]), "+f"((C)[3]) \
        : "r"((A)[0]), "r"((A)[1]), "r"((A)[2]), "r"((A)[3]), "r"(b0v), "r"(b1v))

// sat-FMA: clamp(a*5 + c, 0, 1)  == cumulative-histogram ramp
static __device__ __forceinline__ float fma_sat5(float a, float c) {
    float r;
    asm("fma.rn.sat.f32 %0, %1, %2, %3;" : "=f"(r) : "f"(a), "f"(5.0f), "f"(c));
    return r;
}

// ---------------- small kernels ----------------
__global__ void zero_kernel() {
    int i = blockIdx.x * blockDim.x + threadIdx.x;
    int stride = gridDim.x * blockDim.x;
    for (int idx = i; idx < N_SAMP * HP; idx += stride) { g_all[idx] = 0.0f; g_pos[idx] = 0.0f; }
    for (int idx = i; idx < 8192; idx += stride) g_cls[idx] = 0;
    if (i == 0) { g_ap_sum = 0.0f; g_nvalid = 0.0f; }
}

__global__ void prep_count_kernel(const float* __restrict__ X, const int* __restrict__ labels) {
    int i = blockIdx.x * blockDim.x + threadIdx.x;     // N_SAMP * 64
    if (i < N_SAMP * (EMB / 2)) {
        float2 v = ((const float2*)X)[i];
        ((__nv_bfloat162*)g_Xb)[i] = __float22bfloat162_rn(v);
    }
    if (i < N_SAMP) {
        int l = labels[i];
        if (l >= 0 && l < 8192) atomicAdd(&g_cls[l], 1);
    }
}

// rare-path handler (positive pairs ~1%, out-of-window tails ~1e-5)
static __device__ __noinline__ void rare_elem(float dot, int lab, int gcol, int grow, int mylab) {
    if (gcol == grow) return;                       // exclude diagonal
    float tv = fmaf(dot, -5.0f, 5.0f);              // 2.5 * dist2
    if (lab == mylab) {
        float tp = fmaxf(tv, 0.0f);
        int l0 = min((int)tp, 9);
        float fr = tp - (float)l0;
        atomicAdd(&g_pos[grow * HP + l0],     1.0f - fr);
        atomicAdd(&g_pos[grow * HP + l0 + 1], fr);
    }
    if (tv < 3.0f || tv > 7.0f) {                   // raw tail bins
        #pragma unroll
        for (int b = 0; b <= 2; b++) {
            float w = 1.0f - fabsf(tv - (float)b);
            if (w > 0.0f) atomicAdd(&g_all[grow * HP + b], w);
        }
        #pragma unroll
        for (int b = 8; b <= 10; b++) {
            float w = 1.0f - fabsf(tv - (float)b);
            if (w > 0.0f) atomicAdd(&g_all[grow * HP + b], w);
        }
    }
}

// ---------------- fused HMMA GEMM + sat-FMA cumulative soft-hist ----------------
// grid (CG, 64): blockIdx.y = 128-row block, blockIdx.x = group of TPC 64-col tiles.
// 16 warps, 8(m) x 2(n) warp grid, warp tile 16x32, CTA tile 128x64.
extern __shared__ char smem_raw[];

__global__ __launch_bounds__(THREADS, 2)
void hist_kernel(const int* __restrict__ labels) {
    const int tid  = threadIdx.x;
    const int lane = tid & 31;
    const int warp = tid >> 5;
    const int wm   = warp >> 1;          // 0..7: 16-row slice
    const int wn   = warp & 1;           // 0..1: 32-col half
    const int rb   = blockIdx.y;
    const int cg   = blockIdx.x;
    const int rowG = rb * 128;

    const uint32_t uS = s2u(smem_raw);
    const uint32_t uA = uS;
    const uint32_t uBb[2] = { uS + A_SM, uS + A_SM + B_SM };
    const uint32_t uLab = uS + A_SM + 2 * B_SM;          // int[2][CTILE]
    int* sLab = (int*)(smem_raw + A_SM + 2 * B_SM);

    // ---- load A tile (128x128) + B tile 0 (64x128) via cp.async ----
    {
        const char* gA = (const char*)(g_Xb + (size_t)rb * 128 * EMB);
        for (int i = tid; i < 2048; i += THREADS) {
            int row = i >> 4, c = i & 15;
            CP_ASYNC16(uA + row * PB + c * 16, gA + row * 256 + c * 16);
        }
        int sc = cg * (TPC * CTILE);
        const char* gB = (const char*)(g_Xb + (size_t)sc * EMB);
        for (int i = tid; i < 1024; i += THREADS) {
            int row = i >> 4, c = i & 15;
            CP_ASYNC16(uBb[0] + row * PB + c * 16, gB + row * 256 + c * 16);
        }
        if (tid < CTILE) sLab[tid] = labels[sc + tid];
    }
    CP_COMMIT();
    CP_WAIT0();
    __syncthreads();

    const int g  = lane >> 2;
    const int tq = lane & 3;

    int lrow[2], myLab[2];
    lrow[0] = wm * 16 + g;  lrow[1] = lrow[0] + 8;
    myLab[0] = labels[rowG + lrow[0]];
    myLab[1] = labels[rowG + lrow[1]];

    float h[2][5];                       // cumulative C[3..7] per row
    #pragma unroll
    for (int r = 0; r < 2; r++)
        #pragma unroll
        for (int b = 0; b < 5; b++) h[r][b] = 0.0f;

    const uint32_t aBase = uA + (uint32_t)((wm * 16 + (lane & 15)) * PB + (lane >> 4) * 16);
    const uint32_t bRowOff = (uint32_t)((wn * 32 + (lane & 7) + ((lane >> 4) & 1) * 8) * PB
                                        + ((lane >> 3) & 1) * 16);
    const uint32_t labCol = uLab + (uint32_t)((wn * 32 + tq * 2) * 4);

    #pragma unroll 1
    for (int t = 0; t < TPC; t++) {
        const int buf = t & 1;

        // prefetch B[t+1]
        if (t + 1 < TPC) {
            int sc = cg * (TPC * CTILE) + (t + 1) * CTILE;
            const char* gB = (const char*)(g_Xb + (size_t)sc * EMB);
            uint32_t dB = uBb[buf ^ 1];
            for (int i = tid; i < 1024; i += THREADS) {
                int row = i >> 4, c = i & 15;
                CP_ASYNC16(dB + row * PB + c * 16, gB + row * 256 + c * 16);
            }
            CP_COMMIT();
            if (tid < CTILE) sLab[(buf ^ 1) * CTILE + tid] = labels[sc + tid];
        }

        // ---- GEMM: 128x64 tile, warp computes 16x32 ----
        float acc[4][4];
        #pragma unroll
        for (int j = 0; j < 4; j++)
            #pragma unroll
            for (int e = 0; e < 4; e++) acc[j][e] = 0.0f;

        const uint32_t uBt = uBb[buf] + bRowOff;
        #pragma unroll
        for (int kc = 0; kc < 8; kc++) {
            uint32_t A0[4], B0[4], B1[4];
            LDSM4(A0, aBase + kc * 32);
            LDSM4(B0, uBt + kc * 32);             // n-tiles 0,1
            LDSM4(B1, uBt + 16 * PB + kc * 32);   // n-tiles 2,3
            MMA16816(acc[0], A0, B0[0], B0[1]);
            MMA16816(acc[1], A0, B0[2], B0[3]);
            MMA16816(acc[2], A0, B1[0], B1[1]);
            MMA16816(acc[3], A0, B1[2], B1[3]);
        }

        // ---- epilogue: cumulative sat-FMA binning of 16 dot products ----
        // C[b] += clamp((b+1) - t, 0, 1) = sat(5*dot + (b-4)),  b = 3..7
        const int colBase = cg * (TPC * CTILE) + t * CTILE;
        const uint32_t labT = labCol + (uint32_t)(buf * CTILE * 4);

        #pragma unroll
        for (int j = 0; j < 4; j++) {
            int cl0, cl1;
            asm("ld.shared.v2.u32 {%0,%1}, [%2];" : "=r"(cl0), "=r"(cl1)
                : "r"(labT + (uint32_t)(j * 32)));
            #pragma unroll
            for (int e = 0; e < 4; e++) {
                const int ri = e >> 1;
                const int li = e & 1;
                float dot = acc[j][e];
                #pragma unroll
                for (int b = 0; b < 5; b++)
                    h[ri][b] += fma_sat5(dot, (float)(b - 1));   // b-1 = (b+3)-4
                int clab = li ? cl1 : cl0;
                bool rare = (fabsf(dot) > 0.4f) | (clab == myLab[ri]);
                if (__builtin_expect(rare, 0)) {
                    int gcol = colBase + wn * 32 + j * 8 + tq * 2 + li;
                    rare_elem(dot, clab, gcol, rowG + lrow[ri], myLab[ri]);
                }
            }
        }

        CP_WAIT0();
        __syncthreads();
    }

    // flush cumulative hists (bins 3..7)
    #pragma unroll
    for (int ri = 0; ri < 2; ri++) {
        int grow = rowG + lrow[ri];
        #pragma unroll
        for (int b = 0; b < 5; b++)
            atomicAdd(&g_all[grow * HP + 3 + b], h[ri][b]);
    }
}

// ---------------- finalize (parallel) ----------------
__global__ void finalize_kernel(const int* __restrict__ labels) {
    int i = blockIdx.x * blockDim.x + threadIdx.x;
    float val = 0.0f, valid = 0.0f;
    if (i < N_SAMP) {
        float4 a0 = *(const float4*)&g_all[i * HP + 0];
        float4 a1 = *(const float4*)&g_all[i * HP + 4];
        float4 a2 = *(const float4*)&g_all[i * HP + 8];
        // raw bins 0..2; cumulative C[3..7] (includes diagonal: exactly 1 each)
        float h0 = a0.x, h1 = a0.y, h2 = a0.z;
        float C3 = a0.w - 1.0f, C4 = a1.x - 1.0f, C5 = a1.y - 1.0f,
              C6 = a1.z - 1.0f, C7 = a1.w - 1.0f;
        float aA[12];
        aA[0] = h0; aA[1] = h1; aA[2] = h2;
        aA[3] = C3 - (h0 + h1 + h2);
        aA[4] = C4 - C3; aA[5] = C5 - C4; aA[6] = C6 - C5; aA[7] = C7 - C6;
        aA[8] = a2.x; aA[9] = a2.y; aA[10] = a2.z; aA[11] = 0.0f;
        float4 p0 = *(const float4*)&g_pos[i * HP + 0];
        float4 p1 = *(const float4*)&g_pos[i * HP + 4];
        float4 p2 = *(const float4*)&g_pos[i * HP + 8];
        float  pA[12] = {p0.x,p0.y,p0.z,p0.w,p1.x,p1.y,p1.z,p1.w,p2.x,p2.y,p2.z,0.0f};
        float Hp = 0.0f, H = 0.0f, ap = 0.0f;
        #pragma unroll
        for (int l = 0; l < LBINS; l++) {
            Hp += pA[l];
            H  += aA[l];
            if (H > 0.0f) ap += pA[l] * Hp / H;
        }
        int np = g_cls[labels[i]] - 1;
        if (np > 0) { val = ap / (float)np; valid = 1.0f; }
    }
    #pragma unroll
    for (int off = 16; off > 0; off >>= 1) {
        val   += __shfl_down_sync(0xffffffffu, val, off);
        valid += __shfl_down_sync(0xffffffffu, valid, off);
    }
    if ((threadIdx.x & 31) == 0) {
        atomicAdd(&g_ap_sum, val);
        atomicAdd(&g_nvalid, valid);
    }
}

__global__ void loss_kernel(float* out) {
    out[0] = 1.0f - g_ap_sum / g_nvalid;
}

// ---------------- launch ----------------
extern "C" void kernel_launch(void* const* d_in, const int* in_sizes, int n_in,
                              void* d_out, int out_size) {
    const float* X      = (const float*)d_in[0];
    const int*   labels = (const int*)d_in[1];
    float*       out    = (float*)d_out;

    const int SMEM = A_SM + 2 * B_SM + 2 * CTILE * (int)sizeof(int) + 64;  // ~70.3 KB
    cudaFuncSetAttribute(hist_kernel, cudaFuncAttributeMaxDynamicSharedMemorySize, SMEM);

    zero_kernel<<<256, 256>>>();
    prep_count_kernel<<<(N_SAMP * (EMB / 2) + 255) / 256, 256>>>(X, labels);

    dim3 grid(CG, 64);            // 512 CTAs, 2 per SM: fills all 148 SMs
    hist_kernel<<<grid, THREADS, SMEM>>>(labels);

    finalize_kernel<<<(N_SAMP + 255) / 256, 256>>>(labels);
    loss_kernel<<<1, 1>>>(out);
}

// round 14
// speedup vs baseline: 1.2612x; 1.1894x over previous
#include <cuda_runtime.h>
#include <cuda_bf16.h>
#include <cstdint>

#define N_SAMP  8192
#define EMB     128
#define NBINS   10
#define LBINS   11
#define HP      16
#define THREADS 512
#define CTILE   64
#define NRB     (N_SAMP / 128)           // 64 row blocks
#define NCT     (N_SAMP / CTILE)         // 128 col tiles
#define TOT_T   (NRB * NCT)              // 8192 work items
#define NCTA    296                      // 148 SMs x 2 CTAs
#define PB      272                      // smem tile row pitch (bytes)
#define A_SM    (128 * PB)
#define B_SM    (CTILE * PB)

// ---------------- device scratch ----------------
__device__ __nv_bfloat16 g_Xb[N_SAMP * EMB];   // bf16 X, CLASS-SORTED rows, K-major
__device__ float g_all[N_SAMP * HP];           // bins 0..2,8..10 raw; 3..7 cumulative
__device__ float g_pos[N_SAMP * HP];
__device__ int   g_cls[8192];                  // class counts
__device__ int   g_cstart[130];                // class start offsets (exclusive scan)
__device__ int   g_perm[N_SAMP];               // sorted pos -> original row
__device__ int   g_plab[N_SAMP];               // label of sorted row
__device__ float g_ap_sum;
__device__ float g_nvalid;

// ---------------- PTX helpers ----------------
static __device__ __forceinline__ uint32_t s2u(const void* p) {
    uint32_t a;
    asm("{ .reg .u64 t; cvta.to.shared.u64 t, %1; cvt.u32.u64 %0, t; }" : "=r"(a) : "l"(p));
    return a;
}
#define CP_ASYNC16(dst, src) \
    asm volatile("cp.async.cg.shared.global [%0], [%1], 16;" :: "r"(dst), "l"(src) : "memory")
#define CP_COMMIT() asm volatile("cp.async.commit_group;" ::: "memory")
#define CP_WAIT0()  asm volatile("cp.async.wait_group 0;" ::: "memory")

#define LDSM4(R, addr) \
    asm volatile("ldmatrix.sync.aligned.m8n8.x4.shared.b16 {%0,%1,%2,%3}, [%4];" \
        : "=r"((R)[0]), "=r"((R)[1]), "=r"((R)[2]), "=r"((R)[3]) : "r"(addr))

#define MMA16816(C, A, b0v, b1v) \
    asm volatile("mma.sync.aligned.m16n8k16.row.col.f32.bf16.bf16.f32 " \
        "{%0,%1,%2,%3},{%4,%5,%6,%7},{%8,%9},{%0,%1,%2,%3};" \
        : "+f"((C)[0]), "+f"((C)[1]), "+f"((C)[2]), "+f"((C)[3]) \
        : "r"((A)[0]), "r"((A)[1]), "r"((A)[2]), "r"((A)[3]), "r"(b0v), "r"(b1v))

static __device__ __forceinline__ float fma_sat5(float a, float c) {
    float r;
    asm("fma.rn.sat.f32 %0, %1, %2, %3;" : "=f"(r) : "f"(a), "f"(5.0f), "f"(c));
    return r;
}

// ---------------- small kernels ----------------
__global__ void zero_kernel() {
    int i = blockIdx.x * blockDim.x + threadIdx.x;
    int stride = gridDim.x * blockDim.x;
    for (int idx = i; idx < N_SAMP * HP; idx += stride) { g_all[idx] = 0.0f; g_pos[idx] = 0.0f; }
    for (int idx = i; idx < 8192; idx += stride) g_cls[idx] = 0;
    if (i == 0) { g_ap_sum = 0.0f; g_nvalid = 0.0f; }
}

__global__ void count_kernel(const int* __restrict__ labels) {
    int i = blockIdx.x * blockDim.x + threadIdx.x;
    if (i < N_SAMP) {
        int l = labels[i];
        if (l >= 0 && l < 8192) atomicAdd(&g_cls[l], 1);
    }
}

// single block: exclusive scan over 128 class bins + counting-sort scatter
__global__ void scan_scatter_kernel(const int* __restrict__ labels) {
    __shared__ int sCur[128];
    int tid = threadIdx.x;
    if (tid == 0) {
        int s = 0;
        for (int c = 0; c < 128; c++) {
            g_cstart[c] = s;
            sCur[c] = s;
            s += g_cls[c];
        }
        g_cstart[128] = s;
        g_cstart[129] = s;
    }
    __syncthreads();
    for (int i = tid; i < N_SAMP; i += blockDim.x) {
        int lab = labels[i];
        int p = atomicAdd(&sCur[lab], 1);
        g_perm[p] = i;
        g_plab[p] = lab;
    }
}

// build permuted bf16 matrix: sorted row p <- X[perm[p]]
__global__ void prep_kernel(const float* __restrict__ X) {
    int i = blockIdx.x * blockDim.x + threadIdx.x;     // N_SAMP * 64
    if (i < N_SAMP * (EMB / 2)) {
        int p = i >> 6, k = i & 63;
        int src = g_perm[p];
        float2 v = ((const float2*)X)[src * 64 + k];
        ((__nv_bfloat162*)g_Xb)[p * 64 + k] = __float22bfloat162_rn(v);
    }
}

// tail-only rare path (fast tiles: no positives, no diagonal possible)
static __device__ __noinline__ void rare_tail(float dot, int grow) {
    float tv = fmaf(dot, -5.0f, 5.0f);
    #pragma unroll
    for (int b = 0; b <= 2; b++) {
        float w = 1.0f - fabsf(tv - (float)b);
        if (w > 0.0f) atomicAdd(&g_all[grow * HP + b], w);
    }
    #pragma unroll
    for (int b = 8; b <= 10; b++) {
        float w = 1.0f - fabsf(tv - (float)b);
        if (w > 0.0f) atomicAdd(&g_all[grow * HP + b], w);
    }
}

// full rare path (slow tiles: positives ~1%, tails, diagonal)
static __device__ __noinline__ void rare_elem(float dot, int lab, int gcol, int grow, int mylab) {
    if (gcol == grow) return;                       // exclude diagonal
    float tv = fmaf(dot, -5.0f, 5.0f);
    if (lab == mylab) {
        float tp = fmaxf(tv, 0.0f);
        int l0 = min((int)tp, 9);
        float fr = tp - (float)l0;
        atomicAdd(&g_pos[grow * HP + l0],     1.0f - fr);
        atomicAdd(&g_pos[grow * HP + l0 + 1], fr);
    }
    if (tv < 3.0f || tv > 7.0f) rare_tail(dot, grow);
}

// ---------------- persistent fused HMMA GEMM + sat-FMA soft-hist ----------------
// 296 CTAs, each walks a contiguous range of (rb, ct) work items, rb-major.
extern __shared__ char smem_raw[];

__global__ __launch_bounds__(THREADS, 2)
void hist_kernel() {
    const int tid  = threadIdx.x;
    const int lane = tid & 31;
    const int warp = tid >> 5;
    const int wm   = warp >> 1;          // 0..7
    const int wn   = warp & 1;           // 0..1

    const int w     = blockIdx.x;
    const int start = (int)(((long long)w * TOT_T) / NCTA);
    const int end   = (int)(((long long)(w + 1) * TOT_T) / NCTA);

    const uint32_t uS = s2u(smem_raw);
    const uint32_t uA = uS;
    const uint32_t uBb[2] = { uS + A_SM, uS + A_SM + B_SM };
    const uint32_t uLab = uS + A_SM + 2 * B_SM;
    int* sLab = (int*)(smem_raw + A_SM + 2 * B_SM);   // [2][CTILE]

    const int g  = lane >> 2;
    const int tq = lane & 3;
    int lrow[2];
    lrow[0] = wm * 16 + g;  lrow[1] = lrow[0] + 8;

    const uint32_t aBase = uA + (uint32_t)((wm * 16 + (lane & 15)) * PB + (lane >> 4) * 16);
    const uint32_t bRowOff = (uint32_t)((wn * 32 + (lane & 7) + ((lane >> 4) & 1) * 8) * PB
                                        + ((lane >> 3) & 1) * 16);
    const uint32_t labCol = uLab + (uint32_t)((wn * 32 + tq * 2) * 4);

    // prologue: prefetch B(start) + its labels
    {
        int sc = (start & (NCT - 1)) * CTILE;
        const char* gB = (const char*)(g_Xb + (size_t)sc * EMB);
        uint32_t dB = uBb[start & 1];
        for (int i = tid; i < 1024; i += THREADS) {
            int row = i >> 4, c = i & 15;
            CP_ASYNC16(dB + row * PB + c * 16, gB + row * 256 + c * 16);
        }
        if (tid < CTILE) sLab[(start & 1) * CTILE + tid] = g_plab[sc + tid];
        CP_COMMIT();
    }

    int cur_rb = -1, rowG = 0, lo = 0, hi = 0;
    int myLab[2] = {0, 0};
    float h[2][5];

    #pragma unroll 1
    for (int t = start; t < end; t++) {
        const int rb  = t >> 7;          // NCT = 128
        const int ct  = t & (NCT - 1);
        const int buf = t & 1;

        if (rb != cur_rb) {
            // flush accumulated hist for previous row block
            if (cur_rb >= 0) {
                #pragma unroll
                for (int ri = 0; ri < 2; ri++) {
                    int grow = rowG + lrow[ri];
                    #pragma unroll
                    for (int b = 0; b < 5; b++)
                        atomicAdd(&g_all[grow * HP + 3 + b], h[ri][b]);
                }
            }
            __syncthreads();                     // all warps done with old A
            const char* gA = (const char*)(g_Xb + (size_t)rb * 128 * EMB);
            for (int i = tid; i < 2048; i += THREADS) {
                int row = i >> 4, c = i & 15;
                CP_ASYNC16(uA + row * PB + c * 16, gA + row * 256 + c * 16);
            }
            CP_COMMIT();
            CP_WAIT0();                          // waits A (and pending B: needed anyway)
            __syncthreads();
            rowG = rb * 128;
            myLab[0] = g_plab[rowG + lrow[0]];
            myLab[1] = g_plab[rowG + lrow[1]];
            lo = g_cstart[g_plab[rowG]];
            hi = g_cstart[g_plab[rowG + 127] + 1];
            #pragma unroll
            for (int r = 0; r < 2; r++)
                #pragma unroll
                for (int b = 0; b < 5; b++) h[r][b] = 0.0f;
            cur_rb = rb;
        }

        // prefetch B(t+1) + labels
        if (t + 1 < end) {
            int sc = ((t + 1) & (NCT - 1)) * CTILE;
            const char* gB = (const char*)(g_Xb + (size_t)sc * EMB);
            uint32_t dB = uBb[buf ^ 1];
            for (int i = tid; i < 1024; i += THREADS) {
                int row = i >> 4, c = i & 15;
                CP_ASYNC16(dB + row * PB + c * 16, gB + row * 256 + c * 16);
            }
            CP_COMMIT();
            if (tid < CTILE) sLab[(buf ^ 1) * CTILE + tid] = g_plab[sc + tid];
        }

        // ---- GEMM: 128x64 tile, warp computes 16x32 ----
        float acc[4][4];
        #pragma unroll
        for (int j = 0; j < 4; j++)
            #pragma unroll
            for (int e = 0; e < 4; e++) acc[j][e] = 0.0f;

        const uint32_t uBt = uBb[buf] + bRowOff;
        #pragma unroll
        for (int kc = 0; kc < 8; kc++) {
            uint32_t A0[4], B0[4], B1[4];
            LDSM4(A0, aBase + kc * 32);
            LDSM4(B0, uBt + kc * 32);
            LDSM4(B1, uBt + 16 * PB + kc * 32);
            MMA16816(acc[0], A0, B0[0], B0[1]);
            MMA16816(acc[1], A0, B0[2], B0[3]);
            MMA16816(acc[2], A0, B1[0], B1[1]);
            MMA16816(acc[3], A0, B1[2], B1[3]);
        }

        // ---- epilogue ----
        const int colBase = ct * CTILE;
        const bool slow = (colBase < hi) && (colBase + CTILE > lo);

        if (!slow) {
            // FAST tile: no positives, no diagonal possible
            #pragma unroll
            for (int j = 0; j < 4; j++) {
                #pragma unroll
                for (int e = 0; e < 4; e++) {
                    const int ri = e >> 1;
                    float dot = acc[j][e];
                    #pragma unroll
                    for (int b = 0; b < 5; b++)
                        h[ri][b] += fma_sat5(dot, (float)(b - 1));
                    if (__builtin_expect(fabsf(dot) > 0.4f, 0))
                        rare_tail(dot, rowG + lrow[ri]);
                }
            }
        } else {
            // SLOW tile: label compares + full rare path
            const uint32_t labT = labCol + (uint32_t)(buf * CTILE * 4);
            #pragma unroll
            for (int j = 0; j < 4; j++) {
                int cl0, cl1;
                asm("ld.shared.v2.u32 {%0,%1}, [%2];" : "=r"(cl0), "=r"(cl1)
                    : "r"(labT + (uint32_t)(j * 32)));
                #pragma unroll
                for (int e = 0; e < 4; e++) {
                    const int ri = e >> 1;
                    const int li = e & 1;
                    float dot = acc[j][e];
                    #pragma unroll
                    for (int b = 0; b < 5; b++)
                        h[ri][b] += fma_sat5(dot, (float)(b - 1));
                    int clab = li ? cl1 : cl0;
                    bool rare = (fabsf(dot) > 0.4f) | (clab == myLab[ri]);
                    if (__builtin_expect(rare, 0)) {
                        int gcol = colBase + wn * 32 + j * 8 + tq * 2 + li;
                        rare_elem(dot, clab, gcol, rowG + lrow[ri], myLab[ri]);
                    }
                }
            }
        }

        CP_WAIT0();
        __syncthreads();
    }

    // final flush
    if (cur_rb >= 0) {
        #pragma unroll
        for (int ri = 0; ri < 2; ri++) {
            int grow = rowG + lrow[ri];
            #pragma unroll
            for (int b = 0; b < 5; b++)
                atomicAdd(&g_all[grow * HP + 3 + b], h[ri][b]);
        }
    }
}

// ---------------- finalize (parallel) ----------------
__global__ void finalize_kernel() {
    int i = blockIdx.x * blockDim.x + threadIdx.x;
    float val = 0.0f, valid = 0.0f;
    if (i < N_SAMP) {
        float4 a0 = *(const float4*)&g_all[i * HP + 0];
        float4 a1 = *(const float4*)&g_all[i * HP + 4];
        float4 a2 = *(const float4*)&g_all[i * HP + 8];
        float h0 = a0.x, h1 = a0.y, h2 = a0.z;
        float C3 = a0.w - 1.0f, C4 = a1.x - 1.0f, C5 = a1.y - 1.0f,
              C6 = a1.z - 1.0f, C7 = a1.w - 1.0f;   // diagonal contributes 1 to each C
        float aA[12];
        aA[0] = h0; aA[1] = h1; aA[2] = h2;
        aA[3] = C3 - (h0 + h1 + h2);
        aA[4] = C4 - C3; aA[5] = C5 - C4; aA[6] = C6 - C5; aA[7] = C7 - C6;
        aA[8] = a2.x; aA[9] = a2.y; aA[10] = a2.z; aA[11] = 0.0f;
        float4 p0 = *(const float4*)&g_pos[i * HP + 0];
        float4 p1 = *(const float4*)&g_pos[i * HP + 4];
        float4 p2 = *(const float4*)&g_pos[i * HP + 8];
        float  pA[12] = {p0.x,p0.y,p0.z,p0.w,p1.x,p1.y,p1.z,p1.w,p2.x,p2.y,p2.z,0.0f};
        float Hp = 0.0f, H = 0.0f, ap = 0.0f;
        #pragma unroll
        for (int l = 0; l < LBINS; l++) {
            Hp += pA[l];
            H  += aA[l];
            if (H > 0.0f) ap += pA[l] * Hp / H;
        }
        int np = g_cls[g_plab[i]] - 1;
        if (np > 0) { val = ap / (float)np; valid = 1.0f; }
    }
    #pragma unroll
    for (int off = 16; off > 0; off >>= 1) {
        val   += __shfl_down_sync(0xffffffffu, val, off);
        valid += __shfl_down_sync(0xffffffffu, valid, off);
    }
    if ((threadIdx.x & 31) == 0) {
        atomicAdd(&g_ap_sum, val);
        atomicAdd(&g_nvalid, valid);
    }
}

__global__ void loss_kernel(float* out) {
    out[0] = 1.0f - g_ap_sum / g_nvalid;
}

// ---------------- launch ----------------
extern "C" void kernel_launch(void* const* d_in, const int* in_sizes, int n_in,
                              void* d_out, int out_size) {
    const float* X      = (const float*)d_in[0];
    const int*   labels = (const int*)d_in[1];
    float*       out    = (float*)d_out;

    const int SMEM = A_SM + 2 * B_SM + 2 * CTILE * (int)sizeof(int) + 64;  // ~70.3 KB
    cudaFuncSetAttribute(hist_kernel, cudaFuncAttributeMaxDynamicSharedMemorySize, SMEM);

    zero_kernel<<<256, 256>>>();
    count_kernel<<<(N_SAMP + 255) / 256, 256>>>(labels);
    scan_scatter_kernel<<<1, 1024>>>(labels);
    prep_kernel<<<(N_SAMP * (EMB / 2) + 255) / 256, 256>>>(X);

    hist_kernel<<<NCTA, THREADS, SMEM>>>();    // 296 CTAs: 2/SM, one balanced wave

    finalize_kernel<<<(N_SAMP + 255) / 256, 256>>>();
    loss_kernel<<<1, 1>>>(out);
}

// round 15
// speedup vs baseline: 1.3253x; 1.0508x over previous
#include <cuda_runtime.h>
#include <cuda_bf16.h>
#include <cstdint>

#define N_SAMP  8192
#define EMB     128
#define LBINS   11
#define HP      16
#define THREADS 512
#define CTILE   64
#define NCT     (N_SAMP / CTILE)         // 128 col tiles
#define TOT_T   ((N_SAMP / 128) * NCT)   // 8192 work items
#define NCTA    296                      // 148 SMs x 2 CTAs
#define A_BYTES 32768                    // 128 rows x 256B
#define B_BYTES 16384                    // 64 rows x 256B

// ---------------- device scratch ----------------
__device__ __nv_bfloat16 g_Xb[N_SAMP * EMB];   // bf16 X, class-sorted rows, PRE-SWIZZLED
__device__ float g_all[N_SAMP * HP];           // bins 0..2,8..10 raw; 3..7 cumulative
__device__ float g_pos[N_SAMP * HP];
__device__ int   g_cls[8192];
__device__ int   g_cstart[130];
__device__ int   g_perm[N_SAMP];
__device__ int   g_plab[N_SAMP];
__device__ float g_ap_sum;
__device__ float g_nvalid;

// ---------------- PTX helpers ----------------
static __device__ __forceinline__ uint32_t s2u(const void* p) {
    uint32_t a;
    asm("{ .reg .u64 t; cvta.to.shared.u64 t, %1; cvt.u32.u64 %0, t; }" : "=r"(a) : "l"(p));
    return a;
}
#define CP_ASYNC16(dst, src) \
    asm volatile("cp.async.cg.shared.global [%0], [%1], 16;" :: "r"(dst), "l"(src) : "memory")
#define CP_COMMIT() asm volatile("cp.async.commit_group;" ::: "memory")
#define CP_WAIT0()  asm volatile("cp.async.wait_group 0;" ::: "memory")

#define MBAR_INIT(m, c) \
    asm volatile("mbarrier.init.shared.b64 [%0], %1;" :: "r"(m), "r"(c) : "memory")
#define MBAR_EXPECT_TX(m, b) \
    asm volatile("mbarrier.arrive.expect_tx.shared.b64 _, [%0], %1;" :: "r"(m), "r"(b) : "memory")
#define BULK_G2S(dst, src, bytes, mbar) \
    asm volatile("cp.async.bulk.shared::cluster.global.mbarrier::complete_tx::bytes [%0], [%1], %2, [%3];" \
        :: "r"(dst), "l"(src), "r"(bytes), "r"(mbar) : "memory")

static __device__ __forceinline__ void mbar_wait(uint32_t mbar, uint32_t parity) {
    asm volatile(
        "{\n\t.reg .pred P;\n"
        "WL_%=:\n\t"
        "mbarrier.try_wait.parity.shared.b64 P, [%0], %1;\n\t"
        "@P bra WD_%=;\n\t"
        "bra WL_%=;\n"
        "WD_%=:\n\t}"
        :: "r"(mbar), "r"(parity) : "memory");
}

#define LDSM4(R, addr) \
    asm volatile("ldmatrix.sync.aligned.m8n8.x4.shared.b16 {%0,%1,%2,%3}, [%4];" \
        : "=r"((R)[0]), "=r"((R)[1]), "=r"((R)[2]), "=r"((R)[3]) : "r"(addr))

#define MMA16816(C, A, b0v, b1v) \
    asm volatile("mma.sync.aligned.m16n8k16.row.col.f32.bf16.bf16.f32 " \
        "{%0,%1,%2,%3},{%4,%5,%6,%7},{%8,%9},{%0,%1,%2,%3};" \
        : "+f"((C)[0]), "+f"((C)[1]), "+f"((C)[2]), "+f"((C)[3]) \
        : "r"((A)[0]), "r"((A)[1]), "r"((A)[2]), "r"((A)[3]), "r"(b0v), "r"(b1v))

static __device__ __forceinline__ float fma_sat5(float a, float c) {
    float r;
    asm("fma.rn.sat.f32 %0, %1, %2, %3;" : "=f"(r) : "f"(a), "f"(5.0f), "f"(c));
    return r;
}

// ---------------- small kernels ----------------
__global__ void zero_kernel() {
    int i = blockIdx.x * blockDim.x + threadIdx.x;
    int stride = gridDim.x * blockDim.x;
    for (int idx = i; idx < N_SAMP * HP; idx += stride) { g_all[idx] = 0.0f; g_pos[idx] = 0.0f; }
    if (i == 0) { g_ap_sum = 0.0f; g_nvalid = 0.0f; }
}

// single block: count + exclusive scan + counting-sort scatter
__global__ void sort_kernel(const int* __restrict__ labels) {
    __shared__ int sCnt[128], sCur[128];
    int tid = threadIdx.x;
    if (tid < 128) sCnt[tid] = 0;
    __syncthreads();
    for (int i = tid; i < N_SAMP; i += blockDim.x)
        atomicAdd(&sCnt[labels[i]], 1);
    __syncthreads();
    if (tid == 0) {
        int s = 0;
        for (int c = 0; c < 128; c++) {
            g_cstart[c] = s;
            sCur[c] = s;
            g_cls[c] = sCnt[c];
            s += sCnt[c];
        }
        g_cstart[128] = s;
        g_cstart[129] = s;
    }
    __syncthreads();
    for (int i = tid; i < N_SAMP; i += blockDim.x) {
        int lab = labels[i];
        int p = atomicAdd(&sCur[lab], 1);
        g_perm[p] = i;
        g_plab[p] = lab;
    }
}

// build permuted bf16 matrix, PRE-SWIZZLED: 16B chunk c of row p stored at c ^ (p & 7)
__global__ void prep_kernel(const float* __restrict__ X) {
    int i = blockIdx.x * blockDim.x + threadIdx.x;     // N_SAMP * 64 (4B pieces)
    if (i < N_SAMP * (EMB / 2)) {
        int p = i >> 6, j = i & 63;
        int src = g_perm[p];
        float2 v = ((const float2*)X)[src * 64 + j];
        uint32_t off = (uint32_t)p * 256 + ((((uint32_t)(j >> 2)) ^ (p & 7)) << 4) + (j & 3) * 4;
        *(__nv_bfloat162*)((char*)g_Xb + off) = __float22bfloat162_rn(v);
    }
}

// tail-only rare path (fast tiles)
static __device__ __noinline__ void rare_tail(float dot, int grow) {
    float tv = fmaf(dot, -5.0f, 5.0f);
    #pragma unroll
    for (int b = 0; b <= 2; b++) {
        float w = 1.0f - fabsf(tv - (float)b);
        if (w > 0.0f) atomicAdd(&g_all[grow * HP + b], w);
    }
    #pragma unroll
    for (int b = 8; b <= 10; b++) {
        float w = 1.0f - fabsf(tv - (float)b);
        if (w > 0.0f) atomicAdd(&g_all[grow * HP + b], w);
    }
}

// full rare path (slow tiles)
static __device__ __noinline__ void rare_elem(float dot, int lab, int gcol, int grow, int mylab) {
    if (gcol == grow) return;
    float tv = fmaf(dot, -5.0f, 5.0f);
    if (lab == mylab) {
        float tp = fmaxf(tv, 0.0f);
        int l0 = min((int)tp, 9);
        float fr = tp - (float)l0;
        atomicAdd(&g_pos[grow * HP + l0],     1.0f - fr);
        atomicAdd(&g_pos[grow * HP + l0 + 1], fr);
    }
    if (tv < 3.0f || tv > 7.0f) rare_tail(dot, grow);
}

// ---------------- persistent fused HMMA GEMM + sat-FMA soft-hist ----------------
extern __shared__ char smem_raw[];

__global__ __launch_bounds__(THREADS, 2)
void hist_kernel() {
    const int tid  = threadIdx.x;
    const int lane = tid & 31;
    const int warp = tid >> 5;
    const int wm   = warp >> 1;          // 0..7
    const int wn   = warp & 1;           // 0..1

    const int w     = blockIdx.x;
    const int start = (int)(((long long)w * TOT_T) / NCTA);
    const int end   = (int)(((long long)(w + 1) * TOT_T) / NCTA);

    const uint32_t uS   = s2u(smem_raw);
    const uint32_t uA   = uS;
    const uint32_t uB0  = uS + A_BYTES;                 // two 16KB B buffers
    const uint32_t uLab = uS + A_BYTES + 2 * B_BYTES;   // int[2][64]
    const uint32_t uMb  = uLab + 512;                   // two mbarriers

    const int g  = lane >> 2;
    const int tq = lane & 3;
    int lrow[2];
    lrow[0] = wm * 16 + g;  lrow[1] = lrow[0] + 8;

    // swizzled ldmatrix addressing
    const int rowA  = wm * 16 + (lane & 15);
    const int selA  = lane >> 4;
    const int maskA = lane & 7;
    const uint32_t aRow = uA + (uint32_t)rowA * 256;
    const int rowB  = wn * 32 + (lane & 7) + ((lane >> 4) & 1) * 8;
    const int selB  = (lane >> 3) & 1;
    const int maskB = lane & 7;
    const uint32_t bRowOff = (uint32_t)rowB * 256;
    const uint32_t labCol = uLab + (uint32_t)((wn * 32 + tq * 2) * 4);

    if (tid == 0) {
        MBAR_INIT(uMb,     1);
        MBAR_INIT(uMb + 8, 1);
    }
    __syncthreads();

    // prologue: bulk-load B(start) + labels
    if (tid == 0) {
        int sc = (start & (NCT - 1)) * CTILE;
        uint32_t b = (uint32_t)(start & 1);
        MBAR_EXPECT_TX(uMb + b * 8, B_BYTES + 256);
        BULK_G2S(uB0 + b * B_BYTES, (const char*)g_Xb + (size_t)sc * 256, B_BYTES, uMb + b * 8);
        BULK_G2S(uLab + b * 256,    (const char*)g_plab + (size_t)sc * 4,  256,    uMb + b * 8);
    }

    int cur_rb = -1, rowG = 0, lo = 0, hi = 0;
    int myLab[2] = {0, 0};
    int phv = 0;                          // bit b = phase of buffer b
    float h[2][5];

    #pragma unroll 1
    for (int t = start; t < end; t++) {
        const int rb  = t >> 7;
        const int ct  = t & (NCT - 1);
        const int buf = t & 1;

        if (rb != cur_rb) {
            if (cur_rb >= 0) {
                #pragma unroll
                for (int ri = 0; ri < 2; ri++) {
                    int grow = rowG + lrow[ri];
                    #pragma unroll
                    for (int b = 0; b < 5; b++)
                        atomicAdd(&g_all[grow * HP + 3 + b], h[ri][b]);
                }
            }
            __syncthreads();
            const char* gA = (const char*)g_Xb + (size_t)rb * 128 * 256;
            for (int i = tid; i < 2048; i += THREADS) {
                int row = i >> 4, c = i & 15;   // source already swizzled: linear copy
                CP_ASYNC16(uA + row * 256 + c * 16, gA + row * 256 + c * 16);
            }
            CP_COMMIT();
            CP_WAIT0();
            __syncthreads();
            rowG = rb * 128;
            myLab[0] = g_plab[rowG + lrow[0]];
            myLab[1] = g_plab[rowG + lrow[1]];
            lo = g_cstart[g_plab[rowG]];
            hi = g_cstart[g_plab[rowG + 127] + 1];
            #pragma unroll
            for (int r = 0; r < 2; r++)
                #pragma unroll
                for (int b = 0; b < 5; b++) h[r][b] = 0.0f;
            cur_rb = rb;
        }

        // producer: bulk-prefetch B(t+1) into other buffer
        if (tid == 0 && t + 1 < end) {
            int sc = ((t + 1) & (NCT - 1)) * CTILE;
            uint32_t nb = (uint32_t)((t + 1) & 1);
            MBAR_EXPECT_TX(uMb + nb * 8, B_BYTES + 256);
            BULK_G2S(uB0 + nb * B_BYTES, (const char*)g_Xb + (size_t)sc * 256, B_BYTES, uMb + nb * 8);
            BULK_G2S(uLab + nb * 256,    (const char*)g_plab + (size_t)sc * 4,  256,    uMb + nb * 8);
        }

        // wait for B(t)
        mbar_wait(uMb + buf * 8, (uint32_t)((phv >> buf) & 1));
        phv ^= (1 << buf);

        // ---- GEMM: 128x64 tile, warp computes 16x32 (swizzled LDSM) ----
        float acc[4][4];
        #pragma unroll
        for (int j = 0; j < 4; j++)
            #pragma unroll
            for (int e = 0; e < 4; e++) acc[j][e] = 0.0f;

        const uint32_t uBt = uB0 + (uint32_t)buf * B_BYTES + bRowOff;
        #pragma unroll
        for (int kc = 0; kc < 8; kc++) {
            uint32_t A0[4], B0[4], B1[4];
            uint32_t ca = (uint32_t)(((kc * 2 + selA) ^ maskA) << 4);
            uint32_t cb = (uint32_t)(((kc * 2 + selB) ^ maskB) << 4);
            LDSM4(A0, aRow + ca);
            LDSM4(B0, uBt + cb);
            LDSM4(B1, uBt + 4096 + cb);      // rows +16: same swizzle mask
            MMA16816(acc[0], A0, B0[0], B0[1]);
            MMA16816(acc[1], A0, B0[2], B0[3]);
            MMA16816(acc[2], A0, B1[0], B1[1]);
            MMA16816(acc[3], A0, B1[2], B1[3]);
        }

        // ---- epilogue ----
        const int colBase = ct * CTILE;
        const bool slow = (colBase < hi) && (colBase + CTILE > lo);

        if (!slow) {
            #pragma unroll
            for (int j = 0; j < 4; j++) {
                #pragma unroll
                for (int e = 0; e < 4; e++) {
                    const int ri = e >> 1;
                    float dot = acc[j][e];
                    #pragma unroll
                    for (int b = 0; b < 5; b++)
                        h[ri][b] += fma_sat5(dot, (float)(b - 1));
                    if (__builtin_expect(fabsf(dot) > 0.4f, 0))
                        rare_tail(dot, rowG + lrow[ri]);
                }
            }
        } else {
            const uint32_t labT = labCol + (uint32_t)(buf * 256);
            #pragma unroll
            for (int j = 0; j < 4; j++) {
                int cl0, cl1;
                asm("ld.shared.v2.u32 {%0,%1}, [%2];" : "=r"(cl0), "=r"(cl1)
                    : "r"(labT + (uint32_t)(j * 32)));
                #pragma unroll
                for (int e = 0; e < 4; e++) {
                    const int ri = e >> 1;
                    const int li = e & 1;
                    float dot = acc[j][e];
                    #pragma unroll
                    for (int b = 0; b < 5; b++)
                        h[ri][b] += fma_sat5(dot, (float)(b - 1));
                    int clab = li ? cl1 : cl0;
                    bool rare = (fabsf(dot) > 0.4f) | (clab == myLab[ri]);
                    if (__builtin_expect(rare, 0)) {
                        int gcol = colBase + wn * 32 + j * 8 + tq * 2 + li;
                        rare_elem(dot, clab, gcol, rowG + lrow[ri], myLab[ri]);
                    }
                }
            }
        }

        __syncthreads();   // all reads of buf done before producer reuses it
    }

    if (cur_rb >= 0) {
        #pragma unroll
        for (int ri = 0; ri < 2; ri++) {
            int grow = rowG + lrow[ri];
            #pragma unroll
            for (int b = 0; b < 5; b++)
                atomicAdd(&g_all[grow * HP + 3 + b], h[ri][b]);
        }
    }
}

// ---------------- finalize (parallel) ----------------
__global__ void finalize_kernel() {
    int i = blockIdx.x * blockDim.x + threadIdx.x;
    float val = 0.0f, valid = 0.0f;
    if (i < N_SAMP) {
        float4 a0 = *(const float4*)&g_all[i * HP + 0];
        float4 a1 = *(const float4*)&g_all[i * HP + 4];
        float4 a2 = *(const float4*)&g_all[i * HP + 8];
        float h0 = a0.x, h1 = a0.y, h2 = a0.z;
        float C3 = a0.w - 1.0f, C4 = a1.x - 1.0f, C5 = a1.y - 1.0f,
              C6 = a1.z - 1.0f, C7 = a1.w - 1.0f;   // diagonal contributes 1 to each C
        float aA[12];
        aA[0] = h0; aA[1] = h1; aA[2] = h2;
        aA[3] = C3 - (h0 + h1 + h2);
        aA[4] = C4 - C3; aA[5] = C5 - C4; aA[6] = C6 - C5; aA[7] = C7 - C6;
        aA[8] = a2.x; aA[9] = a2.y; aA[10] = a2.z; aA[11] = 0.0f;
        float4 p0 = *(const float4*)&g_pos[i * HP + 0];
        float4 p1 = *(const float4*)&g_pos[i * HP + 4];
        float4 p2 = *(const float4*)&g_pos[i * HP + 8];
        float  pA[12] = {p0.x,p0.y,p0.z,p0.w,p1.x,p1.y,p1.z,p1.w,p2.x,p2.y,p2.z,0.0f};
        float Hp = 0.0f, H = 0.0f, ap = 0.0f;
        #pragma unroll
        for (int l = 0; l < LBINS; l++) {
            Hp += pA[l];
            H  += aA[l];
            if (H > 0.0f) ap += pA[l] * Hp / H;
        }
        int np = g_cls[g_plab[i]] - 1;
        if (np > 0) { val = ap / (float)np; valid = 1.0f; }
    }
    #pragma unroll
    for (int off = 16; off > 0; off >>= 1) {
        val   += __shfl_down_sync(0xffffffffu, val, off);
        valid += __shfl_down_sync(0xffffffffu, valid, off);
    }
    if ((threadIdx.x & 31) == 0) {
        atomicAdd(&g_ap_sum, val);
        atomicAdd(&g_nvalid, valid);
    }
}

__global__ void loss_kernel(float* out) {
    out[0] = 1.0f - g_ap_sum / g_nvalid;
}

// ---------------- launch ----------------
extern "C" void kernel_launch(void* const* d_in, const int* in_sizes, int n_in,
                              void* d_out, int out_size) {
    const float* X      = (const float*)d_in[0];
    const int*   labels = (const int*)d_in[1];
    float*       out    = (float*)d_out;

    const int SMEM = A_BYTES + 2 * B_BYTES + 512 + 64;   // ~65 KB
    cudaFuncSetAttribute(hist_kernel, cudaFuncAttributeMaxDynamicSharedMemorySize, SMEM);

    zero_kernel<<<256, 256>>>();
    sort_kernel<<<1, 1024>>>(labels);
    prep_kernel<<<(N_SAMP * (EMB / 2) + 255) / 256, 256>>>(X);

    hist_kernel<<<NCTA, THREADS, SMEM>>>();    // 296 CTAs: 2/SM, one balanced wave

    finalize_kernel<<<(N_SAMP + 255) / 256, 256>>>();
    loss_kernel<<<1, 1>>>(out);
}

// round 16
// speedup vs baseline: 1.4471x; 1.0919x over previous
#include <cuda_runtime.h>
#include <cuda_bf16.h>
#include <cstdint>

#define N_SAMP  8192
#define EMB     128
#define LBINS   11
#define HP      16
#define THREADS 512
#define CTILE   64
#define NCT     (N_SAMP / CTILE)         // 128 col tiles
#define TOT_T   ((N_SAMP / 128) * NCT)   // 8192 work items
#define NCTA    296                      // 148 SMs x 2 CTAs
#define A_BYTES 32768                    // 128 rows x 256B
#define B_BYTES 16384                    // 64 rows x 256B

// g_all slot layout (per row, HP=16):
//  0..2  raw tail bins 0..2 (rare atomics)
//  3     R1 = sum sat(u-1)   == C3
//  4     B4 = sum sat(u)     == C4
//  5     Sd = sum dot        (C5 via formula)
//  6     R2 = sum sat(-u-1)  (C6 = C - R2)
//  7     corr7 accumulator   (C7 = C + corr7)
//  8..10 raw tail bins 8..10
//  11    corr5 accumulator

// ---------------- device scratch ----------------
__device__ __nv_bfloat16 g_Xb[N_SAMP * EMB];   // bf16 X, class-sorted rows, PRE-SWIZZLED
__device__ float g_all[N_SAMP * HP];
__device__ float g_pos[N_SAMP * HP];
__device__ int   g_cls[8192];
__device__ int   g_cstart[130];
__device__ int   g_perm[N_SAMP];
__device__ int   g_plab[N_SAMP];
__device__ float g_ap_sum;
__device__ float g_nvalid;

// ---------------- PTX helpers ----------------
static __device__ __forceinline__ uint32_t s2u(const void* p) {
    uint32_t a;
    asm("{ .reg .u64 t; cvta.to.shared.u64 t, %1; cvt.u32.u64 %0, t; }" : "=r"(a) : "l"(p));
    return a;
}
#define CP_ASYNC16(dst, src) \
    asm volatile("cp.async.cg.shared.global [%0], [%1], 16;" :: "r"(dst), "l"(src) : "memory")
#define CP_COMMIT() asm volatile("cp.async.commit_group;" ::: "memory")
#define CP_WAIT0()  asm volatile("cp.async.wait_group 0;" ::: "memory")

#define MBAR_INIT(m, c) \
    asm volatile("mbarrier.init.shared.b64 [%0], %1;" :: "r"(m), "r"(c) : "memory")
#define MBAR_EXPECT_TX(m, b) \
    asm volatile("mbarrier.arrive.expect_tx.shared.b64 _, [%0], %1;" :: "r"(m), "r"(b) : "memory")
#define BULK_G2S(dst, src, bytes, mbar) \
    asm volatile("cp.async.bulk.shared::cluster.global.mbarrier::complete_tx::bytes [%0], [%1], %2, [%3];" \
        :: "r"(dst), "l"(src), "r"(bytes), "r"(mbar) : "memory")

static __device__ __forceinline__ void mbar_wait(uint32_t mbar, uint32_t parity) {
    asm volatile(
        "{\n\t.reg .pred P;\n"
        "WL_%=:\n\t"
        "mbarrier.try_wait.parity.shared.b64 P, [%0], %1;\n\t"
        "@P bra WD_%=;\n\t"
        "bra WL_%=;\n"
        "WD_%=:\n\t}"
        :: "r"(mbar), "r"(parity) : "memory");
}

#define LDSM4(R, addr) \
    asm volatile("ldmatrix.sync.aligned.m8n8.x4.shared.b16 {%0,%1,%2,%3}, [%4];" \
        : "=r"((R)[0]), "=r"((R)[1]), "=r"((R)[2]), "=r"((R)[3]) : "r"(addr))

#define MMA16816(C, A, b0v, b1v) \
    asm volatile("mma.sync.aligned.m16n8k16.row.col.f32.bf16.bf16.f32 " \
        "{%0,%1,%2,%3},{%4,%5,%6,%7},{%8,%9},{%0,%1,%2,%3};" \
        : "+f"((C)[0]), "+f"((C)[1]), "+f"((C)[2]), "+f"((C)[3]) \
        : "r"((A)[0]), "r"((A)[1]), "r"((A)[2]), "r"((A)[3]), "r"(b0v), "r"(b1v))

static __device__ __forceinline__ float fma_sat5(float a, float c) {
    float r;
    asm("fma.rn.sat.f32 %0, %1, %2, %3;" : "=f"(r) : "f"(a), "f"(5.0f), "f"(c));
    return r;
}
static __device__ __forceinline__ float fma_satm5(float a, float c) {
    float r;
    asm("fma.rn.sat.f32 %0, %1, %2, %3;" : "=f"(r) : "f"(a), "f"(-5.0f), "f"(c));
    return r;
}

// ---------------- small kernels ----------------
__global__ void zero_kernel() {
    int i = blockIdx.x * blockDim.x + threadIdx.x;
    int stride = gridDim.x * blockDim.x;
    for (int idx = i; idx < N_SAMP * HP; idx += stride) { g_all[idx] = 0.0f; g_pos[idx] = 0.0f; }
    if (i == 0) { g_ap_sum = 0.0f; g_nvalid = 0.0f; }
}

__global__ void sort_kernel(const int* __restrict__ labels) {
    __shared__ int sCnt[128], sCur[128];
    int tid = threadIdx.x;
    if (tid < 128) sCnt[tid] = 0;
    __syncthreads();
    for (int i = tid; i < N_SAMP; i += blockDim.x)
        atomicAdd(&sCnt[labels[i]], 1);
    __syncthreads();
    if (tid == 0) {
        int s = 0;
        for (int c = 0; c < 128; c++) {
            g_cstart[c] = s;
            sCur[c] = s;
            g_cls[c] = sCnt[c];
            s += sCnt[c];
        }
        g_cstart[128] = s;
        g_cstart[129] = s;
    }
    __syncthreads();
    for (int i = tid; i < N_SAMP; i += blockDim.x) {
        int lab = labels[i];
        int p = atomicAdd(&sCur[lab], 1);
        g_perm[p] = i;
        g_plab[p] = lab;
    }
}

__global__ void prep_kernel(const float* __restrict__ X) {
    int i = blockIdx.x * blockDim.x + threadIdx.x;
    if (i < N_SAMP * (EMB / 2)) {
        int p = i >> 6, j = i & 63;
        int src = g_perm[p];
        float2 v = ((const float2*)X)[src * 64 + j];
        uint32_t off = (uint32_t)p * 256 + ((((uint32_t)(j >> 2)) ^ (p & 7)) << 4) + (j & 3) * 4;
        *(__nv_bfloat162*)((char*)g_Xb + off) = __float22bfloat162_rn(v);
    }
}

// corrections + tail bins for |dot| > 0.4 (non-diagonal)
static __device__ __noinline__ void rare_tail(float dot, int grow) {
    float tv = fmaf(dot, -5.0f, 5.0f);               // t = 2.5*dist2
    #pragma unroll
    for (int b = 0; b <= 2; b++) {
        float w = 1.0f - fabsf(tv - (float)b);
        if (w > 0.0f) atomicAdd(&g_all[grow * HP + b], w);
    }
    #pragma unroll
    for (int b = 8; b <= 10; b++) {
        float w = 1.0f - fabsf(tv - (float)b);
        if (w > 0.0f) atomicAdd(&g_all[grow * HP + b], w);
    }
    // C5 correction: truth sat(u+1) vs formula-implied (u+1) - sat(u-1) + sat(-u-1) - sat(u)
    float u    = 5.0f * dot;
    float s_m1 = fma_sat5(dot, -1.0f);
    float s_0  = fma_sat5(dot,  0.0f);
    float s_p1 = fma_sat5(dot,  1.0f);
    float s_n  = fma_satm5(dot, -1.0f);
    float corr5 = s_p1 - (u + 1.0f - s_m1 + s_n - s_0);
    float corr7 = fma_sat5(dot, 3.0f) - 1.0f;
    if (corr5 != 0.0f) atomicAdd(&g_all[grow * HP + 11], corr5);
    if (corr7 != 0.0f) atomicAdd(&g_all[grow * HP + 7],  corr7);
}

// slow-tile rare path: diagonal removal, positives, tails+corrections
static __device__ __noinline__ void rare_elem(float dot, int lab, int gcol, int grow, int mylab) {
    if (gcol == grow) {
        // diagonal: subtract its main-path tracker contributions
        atomicAdd(&g_all[grow * HP + 3], -fma_sat5(dot, -1.0f));
        atomicAdd(&g_all[grow * HP + 4], -fma_sat5(dot,  0.0f));
        atomicAdd(&g_all[grow * HP + 5], -dot);
        atomicAdd(&g_all[grow * HP + 6], -fma_satm5(dot, -1.0f));
        return;
    }
    if (lab == mylab) {
        float tv = fmaf(dot, -5.0f, 5.0f);
        float tp = fmaxf(tv, 0.0f);
        int l0 = min((int)tp, 9);
        float fr = tp - (float)l0;
        atomicAdd(&g_pos[grow * HP + l0],     1.0f - fr);
        atomicAdd(&g_pos[grow * HP + l0 + 1], fr);
    }
    if (fabsf(dot) > 0.4f) rare_tail(dot, grow);
}

// ---------------- persistent fused HMMA GEMM + tracker soft-hist ----------------
extern __shared__ char smem_raw[];

__global__ __launch_bounds__(THREADS, 2)
void hist_kernel() {
    const int tid  = threadIdx.x;
    const int lane = tid & 31;
    const int warp = tid >> 5;
    const int wm   = warp >> 1;          // 0..7
    const int wn   = warp & 1;           // 0..1

    const int w     = blockIdx.x;
    const int start = (int)(((long long)w * TOT_T) / NCTA);
    const int end   = (int)(((long long)(w + 1) * TOT_T) / NCTA);

    const uint32_t uS   = s2u(smem_raw);
    const uint32_t uA   = uS;
    const uint32_t uB0  = uS + A_BYTES;
    const uint32_t uLab = uS + A_BYTES + 2 * B_BYTES;   // int[2][64]
    const uint32_t uMb  = uLab + 512;

    const int g  = lane >> 2;
    const int tq = lane & 3;
    int lrow[2];
    lrow[0] = wm * 16 + g;  lrow[1] = lrow[0] + 8;

    const int rowA  = wm * 16 + (lane & 15);
    const int selA  = lane >> 4;
    const int maskA = lane & 7;
    const uint32_t aRow = uA + (uint32_t)rowA * 256;
    const int rowB  = wn * 32 + (lane & 7) + ((lane >> 4) & 1) * 8;
    const int selB  = (lane >> 3) & 1;
    const int maskB = lane & 7;
    const uint32_t bRowOff = (uint32_t)rowB * 256;
    const uint32_t labCol = uLab + (uint32_t)((wn * 32 + tq * 2) * 4);

    if (tid == 0) {
        MBAR_INIT(uMb,     1);
        MBAR_INIT(uMb + 8, 1);
    }
    __syncthreads();

    if (tid == 0) {
        int sc = (start & (NCT - 1)) * CTILE;
        uint32_t b = (uint32_t)(start & 1);
        MBAR_EXPECT_TX(uMb + b * 8, B_BYTES + 256);
        BULK_G2S(uB0 + b * B_BYTES, (const char*)g_Xb + (size_t)sc * 256, B_BYTES, uMb + b * 8);
        BULK_G2S(uLab + b * 256,    (const char*)g_plab + (size_t)sc * 4,  256,    uMb + b * 8);
    }

    int cur_rb = -1, rowG = 0, lo = 0, hi = 0;
    int myLab[2] = {0, 0};
    int phv = 0;
    float tk[2][4];                      // R1, B4, Sd, R2 per row

    #pragma unroll 1
    for (int t = start; t < end; t++) {
        const int rb  = t >> 7;
        const int ct  = t & (NCT - 1);
        const int buf = t & 1;

        if (rb != cur_rb) {
            if (cur_rb >= 0) {
                #pragma unroll
                for (int ri = 0; ri < 2; ri++) {
                    int grow = rowG + lrow[ri];
                    atomicAdd(&g_all[grow * HP + 3], tk[ri][0]);
                    atomicAdd(&g_all[grow * HP + 4], tk[ri][1]);
                    atomicAdd(&g_all[grow * HP + 5], tk[ri][2]);
                    atomicAdd(&g_all[grow * HP + 6], tk[ri][3]);
                }
            }
            __syncthreads();
            const char* gA = (const char*)g_Xb + (size_t)rb * 128 * 256;
            for (int i = tid; i < 2048; i += THREADS) {
                int row = i >> 4, c = i & 15;
                CP_ASYNC16(uA + row * 256 + c * 16, gA + row * 256 + c * 16);
            }
            CP_COMMIT();
            CP_WAIT0();
            __syncthreads();
            rowG = rb * 128;
            myLab[0] = g_plab[rowG + lrow[0]];
            myLab[1] = g_plab[rowG + lrow[1]];
            lo = g_cstart[g_plab[rowG]];
            hi = g_cstart[g_plab[rowG + 127] + 1];
            #pragma unroll
            for (int r = 0; r < 2; r++)
                #pragma unroll
                for (int b = 0; b < 4; b++) tk[r][b] = 0.0f;
            cur_rb = rb;
        }

        if (tid == 0 && t + 1 < end) {
            int sc = ((t + 1) & (NCT - 1)) * CTILE;
            uint32_t nb = (uint32_t)((t + 1) & 1);
            MBAR_EXPECT_TX(uMb + nb * 8, B_BYTES + 256);
            BULK_G2S(uB0 + nb * B_BYTES, (const char*)g_Xb + (size_t)sc * 256, B_BYTES, uMb + nb * 8);
            BULK_G2S(uLab + nb * 256,    (const char*)g_plab + (size_t)sc * 4,  256,    uMb + nb * 8);
        }

        mbar_wait(uMb + buf * 8, (uint32_t)((phv >> buf) & 1));
        phv ^= (1 << buf);

        // ---- GEMM ----
        float acc[4][4];
        #pragma unroll
        for (int j = 0; j < 4; j++)
            #pragma unroll
            for (int e = 0; e < 4; e++) acc[j][e] = 0.0f;

        const uint32_t uBt = uB0 + (uint32_t)buf * B_BYTES + bRowOff;
        #pragma unroll
        for (int kc = 0; kc < 8; kc++) {
            uint32_t A0[4], B0[4], B1[4];
            uint32_t ca = (uint32_t)(((kc * 2 + selA) ^ maskA) << 4);
            uint32_t cb = (uint32_t)(((kc * 2 + selB) ^ maskB) << 4);
            LDSM4(A0, aRow + ca);
            LDSM4(B0, uBt + cb);
            LDSM4(B1, uBt + 4096 + cb);
            MMA16816(acc[0], A0, B0[0], B0[1]);
            MMA16816(acc[1], A0, B0[2], B0[3]);
            MMA16816(acc[2], A0, B1[0], B1[1]);
            MMA16816(acc[3], A0, B1[2], B1[3]);
        }

        // ---- epilogue: 4-tracker accumulation (7 ops/element) ----
        const int colBase = ct * CTILE;
        const bool slow = (colBase < hi) && (colBase + CTILE > lo);

        if (!slow) {
            #pragma unroll
            for (int j = 0; j < 4; j++) {
                #pragma unroll
                for (int e = 0; e < 4; e++) {
                    const int ri = e >> 1;
                    float dot = acc[j][e];
                    tk[ri][0] += fma_sat5(dot, -1.0f);
                    tk[ri][1] += fma_sat5(dot,  0.0f);
                    tk[ri][2] += dot;
                    tk[ri][3] += fma_satm5(dot, -1.0f);
                    if (__builtin_expect(fabsf(dot) > 0.4f, 0))
                        rare_tail(dot, rowG + lrow[ri]);
                }
            }
        } else {
            const uint32_t labT = labCol + (uint32_t)(buf * 256);
            #pragma unroll
            for (int j = 0; j < 4; j++) {
                int cl0, cl1;
                asm("ld.shared.v2.u32 {%0,%1}, [%2];" : "=r"(cl0), "=r"(cl1)
                    : "r"(labT + (uint32_t)(j * 32)));
                #pragma unroll
                for (int e = 0; e < 4; e++) {
                    const int ri = e >> 1;
                    const int li = e & 1;
                    float dot = acc[j][e];
                    tk[ri][0] += fma_sat5(dot, -1.0f);
                    tk[ri][1] += fma_sat5(dot,  0.0f);
                    tk[ri][2] += dot;
                    tk[ri][3] += fma_satm5(dot, -1.0f);
                    int clab = li ? cl1 : cl0;
                    bool rare = (fabsf(dot) > 0.4f) | (clab == myLab[ri]);
                    if (__builtin_expect(rare, 0)) {
                        int gcol = colBase + wn * 32 + j * 8 + tq * 2 + li;
                        rare_elem(dot, clab, gcol, rowG + lrow[ri], myLab[ri]);
                    }
                }
            }
        }

        __syncthreads();
    }

    if (cur_rb >= 0) {
        #pragma unroll
        for (int ri = 0; ri < 2; ri++) {
            int grow = rowG + lrow[ri];
            atomicAdd(&g_all[grow * HP + 3], tk[ri][0]);
            atomicAdd(&g_all[grow * HP + 4], tk[ri][1]);
            atomicAdd(&g_all[grow * HP + 5], tk[ri][2]);
            atomicAdd(&g_all[grow * HP + 6], tk[ri][3]);
        }
    }
}

// ---------------- finalize (parallel) ----------------
__global__ void finalize_kernel() {
    int i = blockIdx.x * blockDim.x + threadIdx.x;
    float val = 0.0f, valid = 0.0f;
    if (i < N_SAMP) {
        float4 a0 = *(const float4*)&g_all[i * HP + 0];   // tails0..2, R1
        float4 a1 = *(const float4*)&g_all[i * HP + 4];   // B4, Sd, R2, corr7
        float4 a2 = *(const float4*)&g_all[i * HP + 8];   // tails8..10, corr5
        const float C = (float)(N_SAMP - 1);
        float C3 = a0.w;
        float C4 = a1.x;
        float C5 = 5.0f * a1.y + C - a0.w + a1.z - a1.x + a2.w;
        float C6 = C - a1.z;
        float C7 = C + a1.w;
        float h0 = a0.x, h1 = a0.y, h2 = a0.z;
        float aA[12];
        aA[0] = h0; aA[1] = h1; aA[2] = h2;
        aA[3] = C3 - (h0 + h1 + h2);
        aA[4] = C4 - C3; aA[5] = C5 - C4; aA[6] = C6 - C5; aA[7] = C7 - C6;
        aA[8] = a2.x; aA[9] = a2.y; aA[10] = a2.z; aA[11] = 0.0f;
        float4 p0 = *(const float4*)&g_pos[i * HP + 0];
        float4 p1 = *(const float4*)&g_pos[i * HP + 4];
        float4 p2 = *(const float4*)&g_pos[i * HP + 8];
        float  pA[12] = {p0.x,p0.y,p0.z,p0.w,p1.x,p1.y,p1.z,p1.w,p2.x,p2.y,p2.z,0.0f};
        float Hp = 0.0f, H = 0.0f, ap = 0.0f;
        #pragma unroll
        for (int l = 0; l < LBINS; l++) {
            Hp += pA[l];
            H  += aA[l];
            if (H > 0.0f) ap += pA[l] * Hp / H;
        }
        int np = g_cls[g_plab[i]] - 1;
        if (np > 0) { val = ap / (float)np; valid = 1.0f; }
    }
    #pragma unroll
    for (int off = 16; off > 0; off >>= 1) {
        val   += __shfl_down_sync(0xffffffffu, val, off);
        valid += __shfl_down_sync(0xffffffffu, valid, off);
    }
    if ((threadIdx.x & 31) == 0) {
        atomicAdd(&g_ap_sum, val);
        atomicAdd(&g_nvalid, valid);
    }
}

__global__ void loss_kernel(float* out) {
    out[0] = 1.0f - g_ap_sum / g_nvalid;
}

// ---------------- launch ----------------
extern "C" void kernel_launch(void* const* d_in, const int* in_sizes, int n_in,
                              void* d_out, int out_size) {
    const float* X      = (const float*)d_in[0];
    const int*   labels = (const int*)d_in[1];
    float*       out    = (float*)d_out;

    const int SMEM = A_BYTES + 2 * B_BYTES + 512 + 64;
    cudaFuncSetAttribute(hist_kernel, cudaFuncAttributeMaxDynamicSharedMemorySize, SMEM);

    zero_kernel<<<256, 256>>>();
    sort_kernel<<<1, 1024>>>(labels);
    prep_kernel<<<(N_SAMP * (EMB / 2) + 255) / 256, 256>>>(X);

    hist_kernel<<<NCTA, THREADS, SMEM>>>();

    finalize_kernel<<<(N_SAMP + 255) / 256, 256>>>();
    loss_kernel<<<1, 1>>>(out);
}